// round 2
// baseline (speedup 1.0000x reference)
#include <cuda_runtime.h>
#include <cuda_bf16.h>

#define B_ 4
#define N_ 2048
#define E_ 1024
#define H_ 16
#define D_ 64
#define SCALE_ 0.125f   // 1/sqrt(64)

// Scratch (allocation-free rule: __device__ globals)
__device__ float g_Q[(size_t)B_ * N_ * E_];
__device__ float g_K[(size_t)B_ * N_ * E_];
__device__ float g_V[(size_t)B_ * N_ * E_];
__device__ float g_A[(size_t)B_ * N_ * E_];

// ---------------------------------------------------------------------------
// GEMM: C[M,Nn] = X[M,K] @ W[Nn,K]^T (+ bias). Row-major, K contiguous both.
// 128x128 tile, BK=16, 256 threads, 8x8 microtile, float4 everywhere.
// ---------------------------------------------------------------------------
__global__ __launch_bounds__(256) void gemm_nt(
    const float* __restrict__ X, const float* __restrict__ W,
    const float* __restrict__ bias, float* __restrict__ C,
    int M, int Nn, int K)
{
    __shared__ float Xs[16][132];
    __shared__ float Ws[16][132];

    const int tid = threadIdx.x;
    const int bm = blockIdx.y * 128;
    const int bn = blockIdx.x * 128;
    const int lr = tid >> 2;            // 0..63 (load row)
    const int lc = (tid & 3) << 2;      // 0,4,8,12 (load k-offset)
    const int tm = (tid >> 4) << 3;     // 0..120 (compute rows)
    const int tn = (tid & 15) << 3;     // 0..120 (compute cols)

    float acc[8][8];
#pragma unroll
    for (int i = 0; i < 8; i++)
#pragma unroll
        for (int j = 0; j < 8; j++) acc[i][j] = 0.f;

    const float* Xp = X + (size_t)(bm + lr) * K + lc;
    const float* Wp = W + (size_t)(bn + lr) * K + lc;

    for (int k0 = 0; k0 < K; k0 += 16) {
        float4 x0 = *(const float4*)(Xp + k0);
        float4 x1 = *(const float4*)(Xp + k0 + (size_t)64 * K);
        float4 w0 = *(const float4*)(Wp + k0);
        float4 w1 = *(const float4*)(Wp + k0 + (size_t)64 * K);
        __syncthreads();   // previous iteration's smem reads complete
        Xs[lc + 0][lr] = x0.x; Xs[lc + 1][lr] = x0.y;
        Xs[lc + 2][lr] = x0.z; Xs[lc + 3][lr] = x0.w;
        Xs[lc + 0][lr + 64] = x1.x; Xs[lc + 1][lr + 64] = x1.y;
        Xs[lc + 2][lr + 64] = x1.z; Xs[lc + 3][lr + 64] = x1.w;
        Ws[lc + 0][lr] = w0.x; Ws[lc + 1][lr] = w0.y;
        Ws[lc + 2][lr] = w0.z; Ws[lc + 3][lr] = w0.w;
        Ws[lc + 0][lr + 64] = w1.x; Ws[lc + 1][lr + 64] = w1.y;
        Ws[lc + 2][lr + 64] = w1.z; Ws[lc + 3][lr + 64] = w1.w;
        __syncthreads();
#pragma unroll
        for (int k = 0; k < 16; k++) {
            float a[8], b[8];
            *(float4*)&a[0] = *(const float4*)&Xs[k][tm];
            *(float4*)&a[4] = *(const float4*)&Xs[k][tm + 4];
            *(float4*)&b[0] = *(const float4*)&Ws[k][tn];
            *(float4*)&b[4] = *(const float4*)&Ws[k][tn + 4];
#pragma unroll
            for (int i = 0; i < 8; i++)
#pragma unroll
                for (int j = 0; j < 8; j++)
                    acc[i][j] += a[i] * b[j];
        }
    }

#pragma unroll
    for (int i = 0; i < 8; i++) {
        float* Cp = C + (size_t)(bm + tm + i) * Nn + bn + tn;
        float4 v0 = make_float4(acc[i][0], acc[i][1], acc[i][2], acc[i][3]);
        float4 v1 = make_float4(acc[i][4], acc[i][5], acc[i][6], acc[i][7]);
        if (bias != nullptr) {
            const float* bp = bias + bn + tn;
            v0.x += bp[0]; v0.y += bp[1]; v0.z += bp[2]; v0.w += bp[3];
            v1.x += bp[4]; v1.y += bp[5]; v1.z += bp[6]; v1.w += bp[7];
        }
        *(float4*)(Cp) = v0;
        *(float4*)(Cp + 4) = v1;
    }
}

// ---------------------------------------------------------------------------
// Fused causal flash attention, fp32. One block = 64 q-rows of one (b,h).
// 256 threads as 16x16 grid; each thread owns a 4x4 tile of S/O.
// Causal: q-block i only visits k-blocks 0..i; mask applied on diagonal block.
// ---------------------------------------------------------------------------
__global__ __launch_bounds__(256) void attn_kernel(
    const float* __restrict__ Q, const float* __restrict__ K,
    const float* __restrict__ V, float* __restrict__ O)
{
    __shared__ float Qt[64][68];   // Qt[d][r]
    __shared__ float Kt[64][68];   // Kt[d][c]
    __shared__ float Vs[64][68];   // Vs[k][c] row-major
    __shared__ float Pt[64][68];   // Pt[k][r]

    const int tid = threadIdx.x;
    const int iblk = blockIdx.x;
    const int h = blockIdx.y;
    const int b = blockIdx.z;
    const int qbase = iblk * 64;

    const float* Qp = Q + ((size_t)b * N_ + qbase) * E_ + h * D_;
    const float* Kp = K + (size_t)b * N_ * E_ + h * D_;
    const float* Vp = V + (size_t)b * N_ * E_ + h * D_;

    const int ldr = tid >> 2;        // 0..63
    const int ldc = (tid & 3) << 4;  // 0,16,32,48

    // Load + transpose Q tile once
    {
        const float* src = Qp + (size_t)ldr * E_ + ldc;
#pragma unroll
        for (int v = 0; v < 4; v++) {
            float4 q4 = *(const float4*)(src + v * 4);
            Qt[ldc + v * 4 + 0][ldr] = q4.x;
            Qt[ldc + v * 4 + 1][ldr] = q4.y;
            Qt[ldc + v * 4 + 2][ldr] = q4.z;
            Qt[ldc + v * 4 + 3][ldr] = q4.w;
        }
    }

    const int ty = tid >> 4;   // 0..15
    const int tx = tid & 15;   // 0..15
    const int r0 = ty << 2;
    const int c0 = tx << 2;

    float m[4], l[4], acc[4][4];
#pragma unroll
    for (int i = 0; i < 4; i++) {
        m[i] = -1e30f; l[i] = 0.f;
#pragma unroll
        for (int j = 0; j < 4; j++) acc[i][j] = 0.f;
    }

    for (int jblk = 0; jblk <= iblk; jblk++) {
        const int kbase = jblk * 64;
        const float* ksrc = Kp + (size_t)(kbase + ldr) * E_ + ldc;
        const float* vsrc = Vp + (size_t)(kbase + ldr) * E_ + ldc;
        float4 kk[4], vv[4];
#pragma unroll
        for (int v = 0; v < 4; v++) {
            kk[v] = *(const float4*)(ksrc + v * 4);
            vv[v] = *(const float4*)(vsrc + v * 4);
        }
        __syncthreads();   // prior iteration's Kt/Vs/Pt reads complete
#pragma unroll
        for (int v = 0; v < 4; v++) {
            Kt[ldc + v * 4 + 0][ldr] = kk[v].x;
            Kt[ldc + v * 4 + 1][ldr] = kk[v].y;
            Kt[ldc + v * 4 + 2][ldr] = kk[v].z;
            Kt[ldc + v * 4 + 3][ldr] = kk[v].w;
            *(float4*)&Vs[ldr][ldc + v * 4] = vv[v];
        }
        __syncthreads();

        // S[r][c] = SCALE * sum_d Q[r][d]*K[c][d]
        float s[4][4];
#pragma unroll
        for (int i = 0; i < 4; i++)
#pragma unroll
            for (int j = 0; j < 4; j++) s[i][j] = 0.f;
#pragma unroll
        for (int d = 0; d < 64; d++) {
            float4 qa = *(const float4*)&Qt[d][r0];
            float4 kb = *(const float4*)&Kt[d][c0];
            float a4[4] = {qa.x, qa.y, qa.z, qa.w};
            float b4[4] = {kb.x, kb.y, kb.z, kb.w};
#pragma unroll
            for (int i = 0; i < 4; i++)
#pragma unroll
                for (int j = 0; j < 4; j++)
                    s[i][j] += a4[i] * b4[j];
        }
#pragma unroll
        for (int i = 0; i < 4; i++)
#pragma unroll
            for (int j = 0; j < 4; j++) s[i][j] *= SCALE_;
        if (jblk == iblk) {
#pragma unroll
            for (int i = 0; i < 4; i++)
#pragma unroll
                for (int j = 0; j < 4; j++)
                    if (kbase + c0 + j > qbase + r0 + i) s[i][j] = -1e30f;
        }

        // Online softmax (row stats shared across the 16 tx lanes of a row group)
#pragma unroll
        for (int i = 0; i < 4; i++) {
            float rm = fmaxf(fmaxf(s[i][0], s[i][1]), fmaxf(s[i][2], s[i][3]));
#pragma unroll
            for (int o = 1; o < 16; o <<= 1)
                rm = fmaxf(rm, __shfl_xor_sync(0xffffffffu, rm, o));
            float mn = fmaxf(m[i], rm);
            float alpha = __expf(m[i] - mn);
            m[i] = mn;
            float rs = 0.f;
#pragma unroll
            for (int j = 0; j < 4; j++) {
                s[i][j] = __expf(s[i][j] - mn);
                rs += s[i][j];
            }
#pragma unroll
            for (int o = 1; o < 16; o <<= 1)
                rs += __shfl_xor_sync(0xffffffffu, rs, o);
            l[i] = l[i] * alpha + rs;
#pragma unroll
            for (int j = 0; j < 4; j++) acc[i][j] *= alpha;
        }

        // Write P transposed: Pt[c][r]
#pragma unroll
        for (int j = 0; j < 4; j++) {
            float4 pv = make_float4(s[0][j], s[1][j], s[2][j], s[3][j]);
            *(float4*)&Pt[c0 + j][r0] = pv;
        }
        __syncthreads();

        // O[r][c] += sum_k P[r][k] * V[k][c]
#pragma unroll
        for (int k = 0; k < 64; k++) {
            float4 pr = *(const float4*)&Pt[k][r0];
            float4 vc = *(const float4*)&Vs[k][c0];
            float p4[4] = {pr.x, pr.y, pr.z, pr.w};
            float v4[4] = {vc.x, vc.y, vc.z, vc.w};
#pragma unroll
            for (int i = 0; i < 4; i++)
#pragma unroll
                for (int j = 0; j < 4; j++)
                    acc[i][j] += p4[i] * v4[j];
        }
    }

    // Epilogue: normalize and store merged-head layout [B,N,E], col = h*64+c
    float* Op = O + ((size_t)b * N_ + qbase) * E_ + h * D_;
#pragma unroll
    for (int i = 0; i < 4; i++) {
        float inv = 1.f / l[i];
        float4 ov = make_float4(acc[i][0] * inv, acc[i][1] * inv,
                                acc[i][2] * inv, acc[i][3] * inv);
        *(float4*)(Op + (size_t)(r0 + i) * E_ + c0) = ov;
    }
}

// ---------------------------------------------------------------------------
extern "C" void kernel_launch(void* const* d_in, const int* in_sizes, int n_in,
                              void* d_out, int out_size)
{
    const float* xq = (const float*)d_in[0];
    const float* xk = (const float*)d_in[1];
    const float* xv = (const float*)d_in[2];
    // d_in[3] = attn_mask (causal, recomputed analytically) — unused
    const float* Wq = (const float*)d_in[4];
    const float* Wk = (const float*)d_in[5];
    const float* Wv = (const float*)d_in[6];
    const float* Wo = (const float*)d_in[7];
    const float* bo = (const float*)d_in[8];
    float* out = (float*)d_out;

    float *Qb, *Kb, *Vb, *Ab;
    cudaGetSymbolAddress((void**)&Qb, g_Q);
    cudaGetSymbolAddress((void**)&Kb, g_K);
    cudaGetSymbolAddress((void**)&Vb, g_V);
    cudaGetSymbolAddress((void**)&Ab, g_A);

    const int M = B_ * N_;                 // 8192
    dim3 gblock(256);
    dim3 ggrid(E_ / 128, M / 128);         // (8, 64)

    gemm_nt<<<ggrid, gblock>>>(xq, Wq, nullptr, Qb, M, E_, E_);
    gemm_nt<<<ggrid, gblock>>>(xk, Wk, nullptr, Kb, M, E_, E_);
    gemm_nt<<<ggrid, gblock>>>(xv, Wv, nullptr, Vb, M, E_, E_);

    dim3 agrid(N_ / 64, H_, B_);           // (32, 16, 4)
    attn_kernel<<<agrid, gblock>>>(Qb, Kb, Vb, Ab);

    gemm_nt<<<ggrid, gblock>>>(Ab, Wo, bo, out, M, E_, E_);
}

// round 5
// speedup vs baseline: 1.3819x; 1.3819x over previous
#include <cuda_runtime.h>
#include <cuda_bf16.h>
#include <cstdint>

#define B_ 4
#define N_ 2048
#define E_ 1024
#define H_ 16
#define D_ 64
#define SCALE_ 0.125f   // 1/sqrt(64)

// Scratch (allocation-free rule: __device__ globals)
__device__ float g_Q[(size_t)B_ * N_ * E_];
__device__ float g_K[(size_t)B_ * N_ * E_];
__device__ float g_V[(size_t)B_ * N_ * E_];
__device__ float g_A[(size_t)B_ * N_ * E_];

// ===========================================================================
// Tensor-core GEMM via mma.sync (arch-portable HMMA; tcgen05 PTX does not
// assemble under this harness's plain sm_103 ptxas target).
// C[M,Nn] = X[M,K] @ W[Nn,K]^T (+bias), fp32 I/O.
// Precision: X,W -> (hi,lo) bf16; C = Xh*Wh + Xh*Wl + Xl*Wh (fp32 accum).
// CTA tile 128x128, k-chunk 32. 8 warps, warp tile 64x32.
// ===========================================================================
#define BM 128
#define BN 128
#define BKC 32
#define KTOT 1024
#define NCHUNK (KTOT / BKC)
#define LDT 40          // smem row stride in uint16 (80 bytes)

__device__ __forceinline__ uint32_t smem_u32(const void* p) {
    uint32_t a;
    asm("{ .reg .u64 t; cvta.to.shared.u64 t, %1; cvt.u32.u64 %0, t; }"
        : "=r"(a) : "l"(p));
    return a;
}

__device__ __forceinline__ void ldmx4(uint32_t& r0, uint32_t& r1,
                                      uint32_t& r2, uint32_t& r3, uint32_t a) {
    asm volatile("ldmatrix.sync.aligned.m8n8.x4.shared.b16 {%0,%1,%2,%3}, [%4];"
                 : "=r"(r0), "=r"(r1), "=r"(r2), "=r"(r3) : "r"(a));
}

__device__ __forceinline__ void mma16816(float* d, const uint32_t* a,
                                         const uint32_t* b) {
    asm volatile(
        "mma.sync.aligned.m16n8k16.row.col.f32.bf16.bf16.f32 "
        "{%0,%1,%2,%3}, {%4,%5,%6,%7}, {%8,%9}, {%0,%1,%2,%3};"
        : "+f"(d[0]), "+f"(d[1]), "+f"(d[2]), "+f"(d[3])
        : "r"(a[0]), "r"(a[1]), "r"(a[2]), "r"(a[3]), "r"(b[0]), "r"(b[1]));
}

// ldmatrix.x4 lane address for a 16x16 bf16 tile at (row0, kseg0) in a
// [128][LDT] uint16 smem tile. mat = lane>>3: mat0=(r0-7,k0-7) mat1=(r8-15,k0-7)
// mat2=(r0-7,k8-15) mat3=(r8-15,k8-15) -> exactly mma's {a0,a1,a2,a3}.
__device__ __forceinline__ uint32_t lm_addr(uint32_t base_b, int row0, int kseg0) {
    int L = threadIdx.x & 31;
    int mat = L >> 3;
    int r = (L & 7) + ((mat & 1) << 3);
    int ks = kseg0 + (mat >> 1);
    return base_b + (uint32_t)(row0 + r) * (LDT * 2) + ks * 16;
}

__global__ __launch_bounds__(256) void gemm_tc(
    const float* __restrict__ X, const float* __restrict__ W,
    const float* __restrict__ bias, float* __restrict__ C, int Nn)
{
    __shared__ __align__(16) uint16_t sXh[BM * LDT];
    __shared__ __align__(16) uint16_t sXl[BM * LDT];
    __shared__ __align__(16) uint16_t sWh[BN * LDT];
    __shared__ __align__(16) uint16_t sWl[BN * LDT];

    const int tid = threadIdx.x;
    const int bm = blockIdx.y * BM;
    const int bn = blockIdx.x * BN;

    const int lrow = tid >> 1;            // 0..127
    const int kh = (tid & 1) * 16;        // k offset 0 or 16
    const float* Xp = X + (size_t)(bm + lrow) * KTOT + kh;
    const float* Wp = W + (size_t)(bn + lrow) * KTOT + kh;
    const uint32_t sts_off = (uint32_t)lrow * (LDT * 2) + (kh >> 3) * 16;

    const int w = tid >> 5;
    const int wm = w >> 2;                // 0..1
    const int wn = w & 3;                 // 0..3

    const uint32_t bXh = smem_u32(sXh), bXl = smem_u32(sXl);
    const uint32_t bWh = smem_u32(sWh), bWl = smem_u32(sWl);

    float acc[4][4][4];
#pragma unroll
    for (int i = 0; i < 4; i++)
#pragma unroll
        for (int j = 0; j < 4; j++)
#pragma unroll
            for (int t = 0; t < 4; t++) acc[i][j][t] = 0.f;

    float4 xr[4], wr[4];
#pragma unroll
    for (int i = 0; i < 4; i++) {
        xr[i] = *(const float4*)(Xp + i * 4);
        wr[i] = *(const float4*)(Wp + i * 4);
    }

    for (int c = 0; c < NCHUNK; c++) {
        // convert fp32 -> (hi,lo) bf16, store to smem
        uint32_t xh[8], xl[8], wh[8], wl[8];
#pragma unroll
        for (int i = 0; i < 4; i++) {
            float4 x = xr[i];
            __nv_bfloat162 h01 = __floats2bfloat162_rn(x.x, x.y);
            __nv_bfloat162 h23 = __floats2bfloat162_rn(x.z, x.w);
            __nv_bfloat162 l01 = __floats2bfloat162_rn(
                x.x - __bfloat162float(h01.x), x.y - __bfloat162float(h01.y));
            __nv_bfloat162 l23 = __floats2bfloat162_rn(
                x.z - __bfloat162float(h23.x), x.w - __bfloat162float(h23.y));
            xh[i * 2 + 0] = *(uint32_t*)&h01; xh[i * 2 + 1] = *(uint32_t*)&h23;
            xl[i * 2 + 0] = *(uint32_t*)&l01; xl[i * 2 + 1] = *(uint32_t*)&l23;
            float4 ww = wr[i];
            __nv_bfloat162 g01 = __floats2bfloat162_rn(ww.x, ww.y);
            __nv_bfloat162 g23 = __floats2bfloat162_rn(ww.z, ww.w);
            __nv_bfloat162 m01 = __floats2bfloat162_rn(
                ww.x - __bfloat162float(g01.x), ww.y - __bfloat162float(g01.y));
            __nv_bfloat162 m23 = __floats2bfloat162_rn(
                ww.z - __bfloat162float(g23.x), ww.w - __bfloat162float(g23.y));
            wh[i * 2 + 0] = *(uint32_t*)&g01; wh[i * 2 + 1] = *(uint32_t*)&g23;
            wl[i * 2 + 0] = *(uint32_t*)&m01; wl[i * 2 + 1] = *(uint32_t*)&m23;
        }
        *(uint4*)((char*)sXh + sts_off)      = make_uint4(xh[0], xh[1], xh[2], xh[3]);
        *(uint4*)((char*)sXh + sts_off + 16) = make_uint4(xh[4], xh[5], xh[6], xh[7]);
        *(uint4*)((char*)sXl + sts_off)      = make_uint4(xl[0], xl[1], xl[2], xl[3]);
        *(uint4*)((char*)sXl + sts_off + 16) = make_uint4(xl[4], xl[5], xl[6], xl[7]);
        *(uint4*)((char*)sWh + sts_off)      = make_uint4(wh[0], wh[1], wh[2], wh[3]);
        *(uint4*)((char*)sWh + sts_off + 16) = make_uint4(wh[4], wh[5], wh[6], wh[7]);
        *(uint4*)((char*)sWl + sts_off)      = make_uint4(wl[0], wl[1], wl[2], wl[3]);
        *(uint4*)((char*)sWl + sts_off + 16) = make_uint4(wl[4], wl[5], wl[6], wl[7]);
        __syncthreads();

        // prefetch next chunk (LDG in flight during MMA block)
        if (c + 1 < NCHUNK) {
#pragma unroll
            for (int i = 0; i < 4; i++) {
                xr[i] = *(const float4*)(Xp + (c + 1) * BKC + i * 4);
                wr[i] = *(const float4*)(Wp + (c + 1) * BKC + i * 4);
            }
        }

#pragma unroll
        for (int ks = 0; ks < 2; ks++) {
            const int kseg0 = ks * 2;
            uint32_t ah[4][4], al[4][4], bh[4][2], bl[4][2];
#pragma unroll
            for (int mt = 0; mt < 4; mt++) {
                ldmx4(ah[mt][0], ah[mt][1], ah[mt][2], ah[mt][3],
                      lm_addr(bXh, wm * 64 + mt * 16, kseg0));
                ldmx4(al[mt][0], al[mt][1], al[mt][2], al[mt][3],
                      lm_addr(bXl, wm * 64 + mt * 16, kseg0));
            }
#pragma unroll
            for (int np = 0; np < 2; np++) {
                uint32_t r0, r1, r2, r3;
                ldmx4(r0, r1, r2, r3, lm_addr(bWh, wn * 32 + np * 16, kseg0));
                bh[np * 2 + 0][0] = r0; bh[np * 2 + 0][1] = r2;
                bh[np * 2 + 1][0] = r1; bh[np * 2 + 1][1] = r3;
                ldmx4(r0, r1, r2, r3, lm_addr(bWl, wn * 32 + np * 16, kseg0));
                bl[np * 2 + 0][0] = r0; bl[np * 2 + 0][1] = r2;
                bl[np * 2 + 1][0] = r1; bl[np * 2 + 1][1] = r3;
            }
#pragma unroll
            for (int mt = 0; mt < 4; mt++)
#pragma unroll
                for (int nt = 0; nt < 4; nt++) {
                    mma16816(acc[mt][nt], ah[mt], bh[nt]);
                    mma16816(acc[mt][nt], ah[mt], bl[nt]);
                    mma16816(acc[mt][nt], al[mt], bh[nt]);
                }
        }
        __syncthreads();
    }

    // Epilogue: fragment layout d0,d1=(row g, col 2t,2t+1); d2,d3=row g+8.
    const int lid = tid & 31;
    const int grp = lid >> 2;
    const int tig = lid & 3;
#pragma unroll
    for (int mt = 0; mt < 4; mt++) {
#pragma unroll
        for (int nt = 0; nt < 4; nt++) {
            int row = bm + wm * 64 + mt * 16 + grp;
            int col = bn + wn * 32 + nt * 8 + tig * 2;
            float2 v0 = make_float2(acc[mt][nt][0], acc[mt][nt][1]);
            float2 v1 = make_float2(acc[mt][nt][2], acc[mt][nt][3]);
            if (bias != nullptr) {
                float b0 = bias[col], b1 = bias[col + 1];
                v0.x += b0; v0.y += b1; v1.x += b0; v1.y += b1;
            }
            *(float2*)(C + (size_t)row * Nn + col) = v0;
            *(float2*)(C + (size_t)(row + 8) * Nn + col) = v1;
        }
    }
}

// ---------------------------------------------------------------------------
// Fused causal flash attention, fp32 (unchanged — passing baseline).
// ---------------------------------------------------------------------------
__global__ __launch_bounds__(256) void attn_kernel(
    const float* __restrict__ Q, const float* __restrict__ K,
    const float* __restrict__ V, float* __restrict__ O)
{
    __shared__ float Qt[64][68];
    __shared__ float Kt[64][68];
    __shared__ float Vs[64][68];
    __shared__ float Pt[64][68];

    const int tid = threadIdx.x;
    const int iblk = blockIdx.x;
    const int h = blockIdx.y;
    const int b = blockIdx.z;
    const int qbase = iblk * 64;

    const float* Qp = Q + ((size_t)b * N_ + qbase) * E_ + h * D_;
    const float* Kp = K + (size_t)b * N_ * E_ + h * D_;
    const float* Vp = V + (size_t)b * N_ * E_ + h * D_;

    const int ldr = tid >> 2;
    const int ldc = (tid & 3) << 4;

    {
        const float* src = Qp + (size_t)ldr * E_ + ldc;
#pragma unroll
        for (int v = 0; v < 4; v++) {
            float4 q4 = *(const float4*)(src + v * 4);
            Qt[ldc + v * 4 + 0][ldr] = q4.x;
            Qt[ldc + v * 4 + 1][ldr] = q4.y;
            Qt[ldc + v * 4 + 2][ldr] = q4.z;
            Qt[ldc + v * 4 + 3][ldr] = q4.w;
        }
    }

    const int ty = tid >> 4;
    const int tx = tid & 15;
    const int r0 = ty << 2;
    const int c0 = tx << 2;

    float m[4], l[4], acc[4][4];
#pragma unroll
    for (int i = 0; i < 4; i++) {
        m[i] = -1e30f; l[i] = 0.f;
#pragma unroll
        for (int j = 0; j < 4; j++) acc[i][j] = 0.f;
    }

    for (int jblk = 0; jblk <= iblk; jblk++) {
        const int kbase = jblk * 64;
        const float* ksrc = Kp + (size_t)(kbase + ldr) * E_ + ldc;
        const float* vsrc = Vp + (size_t)(kbase + ldr) * E_ + ldc;
        float4 kk[4], vv[4];
#pragma unroll
        for (int v = 0; v < 4; v++) {
            kk[v] = *(const float4*)(ksrc + v * 4);
            vv[v] = *(const float4*)(vsrc + v * 4);
        }
        __syncthreads();
#pragma unroll
        for (int v = 0; v < 4; v++) {
            Kt[ldc + v * 4 + 0][ldr] = kk[v].x;
            Kt[ldc + v * 4 + 1][ldr] = kk[v].y;
            Kt[ldc + v * 4 + 2][ldr] = kk[v].z;
            Kt[ldc + v * 4 + 3][ldr] = kk[v].w;
            *(float4*)&Vs[ldr][ldc + v * 4] = vv[v];
        }
        __syncthreads();

        float s[4][4];
#pragma unroll
        for (int i = 0; i < 4; i++)
#pragma unroll
            for (int j = 0; j < 4; j++) s[i][j] = 0.f;
#pragma unroll
        for (int d = 0; d < 64; d++) {
            float4 qa = *(const float4*)&Qt[d][r0];
            float4 kb = *(const float4*)&Kt[d][c0];
            float a4[4] = {qa.x, qa.y, qa.z, qa.w};
            float b4[4] = {kb.x, kb.y, kb.z, kb.w};
#pragma unroll
            for (int i = 0; i < 4; i++)
#pragma unroll
                for (int j = 0; j < 4; j++)
                    s[i][j] += a4[i] * b4[j];
        }
#pragma unroll
        for (int i = 0; i < 4; i++)
#pragma unroll
            for (int j = 0; j < 4; j++) s[i][j] *= SCALE_;
        if (jblk == iblk) {
#pragma unroll
            for (int i = 0; i < 4; i++)
#pragma unroll
                for (int j = 0; j < 4; j++)
                    if (kbase + c0 + j > qbase + r0 + i) s[i][j] = -1e30f;
        }

#pragma unroll
        for (int i = 0; i < 4; i++) {
            float rm = fmaxf(fmaxf(s[i][0], s[i][1]), fmaxf(s[i][2], s[i][3]));
#pragma unroll
            for (int o = 1; o < 16; o <<= 1)
                rm = fmaxf(rm, __shfl_xor_sync(0xffffffffu, rm, o));
            float mn = fmaxf(m[i], rm);
            float alpha = __expf(m[i] - mn);
            m[i] = mn;
            float rs = 0.f;
#pragma unroll
            for (int j = 0; j < 4; j++) {
                s[i][j] = __expf(s[i][j] - mn);
                rs += s[i][j];
            }
#pragma unroll
            for (int o = 1; o < 16; o <<= 1)
                rs += __shfl_xor_sync(0xffffffffu, rs, o);
            l[i] = l[i] * alpha + rs;
#pragma unroll
            for (int j = 0; j < 4; j++) acc[i][j] *= alpha;
        }

#pragma unroll
        for (int j = 0; j < 4; j++) {
            float4 pv = make_float4(s[0][j], s[1][j], s[2][j], s[3][j]);
            *(float4*)&Pt[c0 + j][r0] = pv;
        }
        __syncthreads();

#pragma unroll
        for (int k = 0; k < 64; k++) {
            float4 pr = *(const float4*)&Pt[k][r0];
            float4 vc = *(const float4*)&Vs[k][c0];
            float p4[4] = {pr.x, pr.y, pr.z, pr.w};
            float v4[4] = {vc.x, vc.y, vc.z, vc.w};
#pragma unroll
            for (int i = 0; i < 4; i++)
#pragma unroll
                for (int j = 0; j < 4; j++)
                    acc[i][j] += p4[i] * v4[j];
        }
    }

    float* Op = O + ((size_t)b * N_ + qbase) * E_ + h * D_;
#pragma unroll
    for (int i = 0; i < 4; i++) {
        float inv = 1.f / l[i];
        float4 ov = make_float4(acc[i][0] * inv, acc[i][1] * inv,
                                acc[i][2] * inv, acc[i][3] * inv);
        *(float4*)(Op + (size_t)(r0 + i) * E_ + c0) = ov;
    }
}

// ---------------------------------------------------------------------------
extern "C" void kernel_launch(void* const* d_in, const int* in_sizes, int n_in,
                              void* d_out, int out_size)
{
    const float* xq = (const float*)d_in[0];
    const float* xk = (const float*)d_in[1];
    const float* xv = (const float*)d_in[2];
    // d_in[3] = attn_mask (causal, recomputed analytically) — unused
    const float* Wq = (const float*)d_in[4];
    const float* Wk = (const float*)d_in[5];
    const float* Wv = (const float*)d_in[6];
    const float* Wo = (const float*)d_in[7];
    const float* bo = (const float*)d_in[8];
    float* out = (float*)d_out;

    float *Qb, *Kb, *Vb, *Ab;
    cudaGetSymbolAddress((void**)&Qb, g_Q);
    cudaGetSymbolAddress((void**)&Kb, g_K);
    cudaGetSymbolAddress((void**)&Vb, g_V);
    cudaGetSymbolAddress((void**)&Ab, g_A);

    const int M = B_ * N_;                 // 8192
    dim3 gblock(256);
    dim3 ggrid(E_ / BN, M / BM);           // (8, 64)

    gemm_tc<<<ggrid, gblock>>>(xq, Wq, nullptr, Qb, E_);
    gemm_tc<<<ggrid, gblock>>>(xk, Wk, nullptr, Kb, E_);
    gemm_tc<<<ggrid, gblock>>>(xv, Wv, nullptr, Vb, E_);

    dim3 agrid(N_ / 64, H_, B_);           // (32, 16, 4)
    attn_kernel<<<agrid, gblock>>>(Qb, Kb, Vb, Ab);

    gemm_tc<<<ggrid, gblock>>>(Ab, Wo, bo, out, E_);
}

// round 6
// speedup vs baseline: 1.4311x; 1.0356x over previous
#include <cuda_runtime.h>
#include <cuda_bf16.h>
#include <cstdint>

#define B_ 4
#define N_ 2048
#define E_ 1024
#define H_ 16
#define D_ 64
#define SCALE_ 0.125f   // 1/sqrt(64)
#define MTOT (B_ * N_)  // 8192

// ---------------------------------------------------------------------------
// Scratch (allocation-free rule: __device__ globals)
// ---------------------------------------------------------------------------
__device__ float g_Q[(size_t)MTOT * E_];
__device__ float g_K[(size_t)MTOT * E_];
__device__ float g_V[(size_t)MTOT * E_];

__device__ __nv_bfloat16 g_xqh[(size_t)MTOT * E_];
__device__ __nv_bfloat16 g_xql[(size_t)MTOT * E_];
__device__ __nv_bfloat16 g_xkh[(size_t)MTOT * E_];
__device__ __nv_bfloat16 g_xkl[(size_t)MTOT * E_];
__device__ __nv_bfloat16 g_xvh[(size_t)MTOT * E_];
__device__ __nv_bfloat16 g_xvl[(size_t)MTOT * E_];
__device__ __nv_bfloat16 g_Ah[(size_t)MTOT * E_];
__device__ __nv_bfloat16 g_Al[(size_t)MTOT * E_];

__device__ __nv_bfloat16 g_Wqh[(size_t)E_ * E_];
__device__ __nv_bfloat16 g_Wql[(size_t)E_ * E_];
__device__ __nv_bfloat16 g_Wkh[(size_t)E_ * E_];
__device__ __nv_bfloat16 g_Wkl[(size_t)E_ * E_];
__device__ __nv_bfloat16 g_Wvh[(size_t)E_ * E_];
__device__ __nv_bfloat16 g_Wvl[(size_t)E_ * E_];
__device__ __nv_bfloat16 g_Woh[(size_t)E_ * E_];
__device__ __nv_bfloat16 g_Wol[(size_t)E_ * E_];

// ---------------------------------------------------------------------------
// Prepass: fp32 -> (hi, lo) bf16 split.  hi = bf16(x), lo = bf16(x - hi).
// ---------------------------------------------------------------------------
__global__ __launch_bounds__(256) void convert_split(
    const float* __restrict__ src, __nv_bfloat16* __restrict__ h,
    __nv_bfloat16* __restrict__ l, int n4)
{
    int i = blockIdx.x * 256 + threadIdx.x;
    if (i >= n4) return;
    float4 v = ((const float4*)src)[i];
    __nv_bfloat162 h01 = __floats2bfloat162_rn(v.x, v.y);
    __nv_bfloat162 h23 = __floats2bfloat162_rn(v.z, v.w);
    __nv_bfloat162 l01 = __floats2bfloat162_rn(
        v.x - __bfloat162float(h01.x), v.y - __bfloat162float(h01.y));
    __nv_bfloat162 l23 = __floats2bfloat162_rn(
        v.z - __bfloat162float(h23.x), v.w - __bfloat162float(h23.y));
    ((uint2*)h)[i] = make_uint2(*(uint32_t*)&h01, *(uint32_t*)&h23);
    ((uint2*)l)[i] = make_uint2(*(uint32_t*)&l01, *(uint32_t*)&l23);
}

// ===========================================================================
// Tensor-core GEMM (mma.sync HMMA), preconverted bf16 hi/lo inputs.
// C[M,Nn] = (Xh+Xl)[M,K] @ (Wh+Wl)[Nn,K]^T (+bias), fp32 accum.
// C = Xh*Wh + Xh*Wl + Xl*Wh.  CTA 128x128, k-chunk 32, double-buffered
// cp.async pipeline. 8 warps, warp tile 64x32.
// ===========================================================================
#define BM 128
#define BN 128
#define BKC 32
#define KTOT 1024
#define NCHUNK (KTOT / BKC)
#define LDT 40                 // smem row stride in uint16 (80 bytes)
#define TILE_B (128 * LDT * 2) // 10240 bytes per tile
#define STAGE_B (4 * TILE_B)   // 40960 bytes per stage
#define GSMEM_SZ (2 * STAGE_B) // 81920

__device__ __forceinline__ uint32_t smem_u32(const void* p) {
    uint32_t a;
    asm("{ .reg .u64 t; cvta.to.shared.u64 t, %1; cvt.u32.u64 %0, t; }"
        : "=r"(a) : "l"(p));
    return a;
}

__device__ __forceinline__ void cp16(uint32_t sa, const void* ga) {
    asm volatile("cp.async.cg.shared.global [%0], [%1], 16;"
                 :: "r"(sa), "l"(ga));
}
__device__ __forceinline__ void cp_commit() {
    asm volatile("cp.async.commit_group;");
}
__device__ __forceinline__ void cp_wait1() {
    asm volatile("cp.async.wait_group 1;");
}
__device__ __forceinline__ void cp_wait0() {
    asm volatile("cp.async.wait_group 0;");
}

__device__ __forceinline__ void ldmx4(uint32_t& r0, uint32_t& r1,
                                      uint32_t& r2, uint32_t& r3, uint32_t a) {
    asm volatile("ldmatrix.sync.aligned.m8n8.x4.shared.b16 {%0,%1,%2,%3}, [%4];"
                 : "=r"(r0), "=r"(r1), "=r"(r2), "=r"(r3) : "r"(a));
}

__device__ __forceinline__ void mma16816(float* d, const uint32_t* a,
                                         const uint32_t* b) {
    asm volatile(
        "mma.sync.aligned.m16n8k16.row.col.f32.bf16.bf16.f32 "
        "{%0,%1,%2,%3}, {%4,%5,%6,%7}, {%8,%9}, {%0,%1,%2,%3};"
        : "+f"(d[0]), "+f"(d[1]), "+f"(d[2]), "+f"(d[3])
        : "r"(a[0]), "r"(a[1]), "r"(a[2]), "r"(a[3]), "r"(b[0]), "r"(b[1]));
}

// ldmatrix.x4 lane address for a 16x16 bf16 tile at (row0, kseg0).
__device__ __forceinline__ uint32_t lm_addr(uint32_t base_b, int row0, int kseg0) {
    int L = threadIdx.x & 31;
    int mat = L >> 3;
    int r = (L & 7) + ((mat & 1) << 3);
    int ks = kseg0 + (mat >> 1);
    return base_b + (uint32_t)(row0 + r) * (LDT * 2) + ks * 16;
}

__global__ __launch_bounds__(256) void gemm_tc(
    const __nv_bfloat16* __restrict__ Xh, const __nv_bfloat16* __restrict__ Xl,
    const __nv_bfloat16* __restrict__ Wh, const __nv_bfloat16* __restrict__ Wl,
    const float* __restrict__ bias, float* __restrict__ C, int Nn)
{
    extern __shared__ char sm[];
    const uint32_t smb = smem_u32(sm);
    const int tid = threadIdx.x;
    const int bm = blockIdx.y * BM;
    const int bn = blockIdx.x * BN;

    const int w = tid >> 5;
    const int wm = w >> 2;                // 0..1
    const int wn = w & 3;                 // 0..3

    // cp.async mapping: seg_id = tid + 256*i; tile = sid>>9 (0:Xh 1:Xl 2:Wh 3:Wl)
    // row = (sid>>2)&127, seg = sid&3.  Lane-consecutive sids -> contiguous 16B.
    const char* tb[4];
    tb[0] = (const char*)(Xh + (size_t)bm * KTOT);
    tb[1] = (const char*)(Xl + (size_t)bm * KTOT);
    tb[2] = (const char*)(Wh + (size_t)bn * KTOT);
    tb[3] = (const char*)(Wl + (size_t)bn * KTOT);

    float acc[4][4][4];
#pragma unroll
    for (int i = 0; i < 4; i++)
#pragma unroll
        for (int j = 0; j < 4; j++)
#pragma unroll
            for (int t = 0; t < 4; t++) acc[i][j][t] = 0.f;

    // issue a full stage of cp.async for chunk c into stage s
    auto issue = [&](int c, int s) {
#pragma unroll
        for (int i = 0; i < 8; i++) {
            int sid = tid + 256 * i;
            int tile = sid >> 9;
            int r = (sid >> 2) & 127;
            int seg = sid & 3;
            const char* base = (tile == 0) ? tb[0] : (tile == 1) ? tb[1]
                             : (tile == 2) ? tb[2] : tb[3];
            uint32_t sa = smb + (uint32_t)s * STAGE_B + (uint32_t)tile * TILE_B
                        + (uint32_t)r * (LDT * 2) + seg * 16;
            const char* ga = base + (size_t)r * (KTOT * 2) + c * (BKC * 2) + seg * 16;
            cp16(sa, ga);
        }
        cp_commit();
    };

    issue(0, 0);

    for (int c = 0; c < NCHUNK; c++) {
        const int st = c & 1;
        if (c + 1 < NCHUNK) {
            issue(c + 1, st ^ 1);
            cp_wait1();
        } else {
            cp_wait0();
        }
        __syncthreads();

        const uint32_t bXh = smb + (uint32_t)st * STAGE_B;
        const uint32_t bXl = bXh + TILE_B;
        const uint32_t bWh = bXh + 2 * TILE_B;
        const uint32_t bWl = bXh + 3 * TILE_B;

#pragma unroll
        for (int ks = 0; ks < 2; ks++) {
            const int kseg0 = ks * 2;
            uint32_t ah[4][4], al[4][4], bh[4][2], bl[4][2];
#pragma unroll
            for (int mt = 0; mt < 4; mt++) {
                ldmx4(ah[mt][0], ah[mt][1], ah[mt][2], ah[mt][3],
                      lm_addr(bXh, wm * 64 + mt * 16, kseg0));
                ldmx4(al[mt][0], al[mt][1], al[mt][2], al[mt][3],
                      lm_addr(bXl, wm * 64 + mt * 16, kseg0));
            }
#pragma unroll
            for (int np = 0; np < 2; np++) {
                uint32_t r0, r1, r2, r3;
                ldmx4(r0, r1, r2, r3, lm_addr(bWh, wn * 32 + np * 16, kseg0));
                bh[np * 2 + 0][0] = r0; bh[np * 2 + 0][1] = r2;
                bh[np * 2 + 1][0] = r1; bh[np * 2 + 1][1] = r3;
                ldmx4(r0, r1, r2, r3, lm_addr(bWl, wn * 32 + np * 16, kseg0));
                bl[np * 2 + 0][0] = r0; bl[np * 2 + 0][1] = r2;
                bl[np * 2 + 1][0] = r1; bl[np * 2 + 1][1] = r3;
            }
#pragma unroll
            for (int mt = 0; mt < 4; mt++)
#pragma unroll
                for (int nt = 0; nt < 4; nt++) {
                    mma16816(acc[mt][nt], ah[mt], bh[nt]);
                    mma16816(acc[mt][nt], ah[mt], bl[nt]);
                    mma16816(acc[mt][nt], al[mt], bh[nt]);
                }
        }
        __syncthreads();
    }

    // Epilogue: d0,d1 = (row g, col 2t,2t+1); d2,d3 = row g+8.
    const int lid = tid & 31;
    const int grp = lid >> 2;
    const int tig = lid & 3;
#pragma unroll
    for (int mt = 0; mt < 4; mt++) {
#pragma unroll
        for (int nt = 0; nt < 4; nt++) {
            int row = bm + wm * 64 + mt * 16 + grp;
            int col = bn + wn * 32 + nt * 8 + tig * 2;
            float2 v0 = make_float2(acc[mt][nt][0], acc[mt][nt][1]);
            float2 v1 = make_float2(acc[mt][nt][2], acc[mt][nt][3]);
            if (bias != nullptr) {
                float b0 = bias[col], b1 = bias[col + 1];
                v0.x += b0; v0.y += b1; v1.x += b0; v1.y += b1;
            }
            *(float2*)(C + (size_t)row * Nn + col) = v0;
            *(float2*)(C + (size_t)(row + 8) * Nn + col) = v1;
        }
    }
}

// ---------------------------------------------------------------------------
// Fused causal flash attention, fp32; epilogue emits (hi,lo) bf16 directly.
// ---------------------------------------------------------------------------
__global__ __launch_bounds__(256) void attn_kernel(
    const float* __restrict__ Q, const float* __restrict__ K,
    const float* __restrict__ V,
    __nv_bfloat16* __restrict__ Oh, __nv_bfloat16* __restrict__ Ol)
{
    __shared__ float Qt[64][68];
    __shared__ float Kt[64][68];
    __shared__ float Vs[64][68];
    __shared__ float Pt[64][68];

    const int tid = threadIdx.x;
    const int iblk = blockIdx.x;
    const int h = blockIdx.y;
    const int b = blockIdx.z;
    const int qbase = iblk * 64;

    const float* Qp = Q + ((size_t)b * N_ + qbase) * E_ + h * D_;
    const float* Kp = K + (size_t)b * N_ * E_ + h * D_;
    const float* Vp = V + (size_t)b * N_ * E_ + h * D_;

    const int ldr = tid >> 2;
    const int ldc = (tid & 3) << 4;

    {
        const float* src = Qp + (size_t)ldr * E_ + ldc;
#pragma unroll
        for (int v = 0; v < 4; v++) {
            float4 q4 = *(const float4*)(src + v * 4);
            Qt[ldc + v * 4 + 0][ldr] = q4.x;
            Qt[ldc + v * 4 + 1][ldr] = q4.y;
            Qt[ldc + v * 4 + 2][ldr] = q4.z;
            Qt[ldc + v * 4 + 3][ldr] = q4.w;
        }
    }

    const int ty = tid >> 4;
    const int tx = tid & 15;
    const int r0 = ty << 2;
    const int c0 = tx << 2;

    float m[4], l[4], acc[4][4];
#pragma unroll
    for (int i = 0; i < 4; i++) {
        m[i] = -1e30f; l[i] = 0.f;
#pragma unroll
        for (int j = 0; j < 4; j++) acc[i][j] = 0.f;
    }

    for (int jblk = 0; jblk <= iblk; jblk++) {
        const int kbase = jblk * 64;
        const float* ksrc = Kp + (size_t)(kbase + ldr) * E_ + ldc;
        const float* vsrc = Vp + (size_t)(kbase + ldr) * E_ + ldc;
        float4 kk[4], vv[4];
#pragma unroll
        for (int v = 0; v < 4; v++) {
            kk[v] = *(const float4*)(ksrc + v * 4);
            vv[v] = *(const float4*)(vsrc + v * 4);
        }
        __syncthreads();
#pragma unroll
        for (int v = 0; v < 4; v++) {
            Kt[ldc + v * 4 + 0][ldr] = kk[v].x;
            Kt[ldc + v * 4 + 1][ldr] = kk[v].y;
            Kt[ldc + v * 4 + 2][ldr] = kk[v].z;
            Kt[ldc + v * 4 + 3][ldr] = kk[v].w;
            *(float4*)&Vs[ldr][ldc + v * 4] = vv[v];
        }
        __syncthreads();

        float s[4][4];
#pragma unroll
        for (int i = 0; i < 4; i++)
#pragma unroll
            for (int j = 0; j < 4; j++) s[i][j] = 0.f;
#pragma unroll
        for (int d = 0; d < 64; d++) {
            float4 qa = *(const float4*)&Qt[d][r0];
            float4 kb = *(const float4*)&Kt[d][c0];
            float a4[4] = {qa.x, qa.y, qa.z, qa.w};
            float b4[4] = {kb.x, kb.y, kb.z, kb.w};
#pragma unroll
            for (int i = 0; i < 4; i++)
#pragma unroll
                for (int j = 0; j < 4; j++)
                    s[i][j] += a4[i] * b4[j];
        }
#pragma unroll
        for (int i = 0; i < 4; i++)
#pragma unroll
            for (int j = 0; j < 4; j++) s[i][j] *= SCALE_;
        if (jblk == iblk) {
#pragma unroll
            for (int i = 0; i < 4; i++)
#pragma unroll
                for (int j = 0; j < 4; j++)
                    if (kbase + c0 + j > qbase + r0 + i) s[i][j] = -1e30f;
        }

#pragma unroll
        for (int i = 0; i < 4; i++) {
            float rm = fmaxf(fmaxf(s[i][0], s[i][1]), fmaxf(s[i][2], s[i][3]));
#pragma unroll
            for (int o = 1; o < 16; o <<= 1)
                rm = fmaxf(rm, __shfl_xor_sync(0xffffffffu, rm, o));
            float mn = fmaxf(m[i], rm);
            float alpha = __expf(m[i] - mn);
            m[i] = mn;
            float rs = 0.f;
#pragma unroll
            for (int j = 0; j < 4; j++) {
                s[i][j] = __expf(s[i][j] - mn);
                rs += s[i][j];
            }
#pragma unroll
            for (int o = 1; o < 16; o <<= 1)
                rs += __shfl_xor_sync(0xffffffffu, rs, o);
            l[i] = l[i] * alpha + rs;
#pragma unroll
            for (int j = 0; j < 4; j++) acc[i][j] *= alpha;
        }

#pragma unroll
        for (int j = 0; j < 4; j++) {
            float4 pv = make_float4(s[0][j], s[1][j], s[2][j], s[3][j]);
            *(float4*)&Pt[c0 + j][r0] = pv;
        }
        __syncthreads();

#pragma unroll
        for (int k = 0; k < 64; k++) {
            float4 pr = *(const float4*)&Pt[k][r0];
            float4 vc = *(const float4*)&Vs[k][c0];
            float p4[4] = {pr.x, pr.y, pr.z, pr.w};
            float v4[4] = {vc.x, vc.y, vc.z, vc.w};
#pragma unroll
            for (int i = 0; i < 4; i++)
#pragma unroll
                for (int j = 0; j < 4; j++)
                    acc[i][j] += p4[i] * v4[j];
        }
    }

    // Epilogue: normalize, split hi/lo bf16, store merged-head [B,N,E].
    const size_t obase = ((size_t)b * N_ + qbase) * E_ + h * D_;
#pragma unroll
    for (int i = 0; i < 4; i++) {
        float inv = 1.f / l[i];
        float o0 = acc[i][0] * inv, o1 = acc[i][1] * inv;
        float o2 = acc[i][2] * inv, o3 = acc[i][3] * inv;
        __nv_bfloat162 h01 = __floats2bfloat162_rn(o0, o1);
        __nv_bfloat162 h23 = __floats2bfloat162_rn(o2, o3);
        __nv_bfloat162 l01 = __floats2bfloat162_rn(
            o0 - __bfloat162float(h01.x), o1 - __bfloat162float(h01.y));
        __nv_bfloat162 l23 = __floats2bfloat162_rn(
            o2 - __bfloat162float(h23.x), o3 - __bfloat162float(h23.y));
        size_t off = obase + (size_t)(r0 + i) * E_ + c0;
        *(uint2*)(Oh + off) = make_uint2(*(uint32_t*)&h01, *(uint32_t*)&h23);
        *(uint2*)(Ol + off) = make_uint2(*(uint32_t*)&l01, *(uint32_t*)&l23);
    }
}

// ---------------------------------------------------------------------------
extern "C" void kernel_launch(void* const* d_in, const int* in_sizes, int n_in,
                              void* d_out, int out_size)
{
    const float* xq = (const float*)d_in[0];
    const float* xk = (const float*)d_in[1];
    const float* xv = (const float*)d_in[2];
    // d_in[3] = attn_mask (causal, recomputed analytically) — unused
    const float* Wq = (const float*)d_in[4];
    const float* Wk = (const float*)d_in[5];
    const float* Wv = (const float*)d_in[6];
    const float* Wo = (const float*)d_in[7];
    const float* bo = (const float*)d_in[8];
    float* out = (float*)d_out;

    float *Qb, *Kb, *Vb;
    cudaGetSymbolAddress((void**)&Qb, g_Q);
    cudaGetSymbolAddress((void**)&Kb, g_K);
    cudaGetSymbolAddress((void**)&Vb, g_V);

    __nv_bfloat16 *xqh, *xql, *xkh, *xkl, *xvh, *xvl, *Ah, *Al;
    __nv_bfloat16 *Wqh, *Wql, *Wkh, *Wkl, *Wvh, *Wvl, *Woh, *Wol;
    cudaGetSymbolAddress((void**)&xqh, g_xqh);
    cudaGetSymbolAddress((void**)&xql, g_xql);
    cudaGetSymbolAddress((void**)&xkh, g_xkh);
    cudaGetSymbolAddress((void**)&xkl, g_xkl);
    cudaGetSymbolAddress((void**)&xvh, g_xvh);
    cudaGetSymbolAddress((void**)&xvl, g_xvl);
    cudaGetSymbolAddress((void**)&Ah, g_Ah);
    cudaGetSymbolAddress((void**)&Al, g_Al);
    cudaGetSymbolAddress((void**)&Wqh, g_Wqh);
    cudaGetSymbolAddress((void**)&Wql, g_Wql);
    cudaGetSymbolAddress((void**)&Wkh, g_Wkh);
    cudaGetSymbolAddress((void**)&Wkl, g_Wkl);
    cudaGetSymbolAddress((void**)&Wvh, g_Wvh);
    cudaGetSymbolAddress((void**)&Wvl, g_Wvl);
    cudaGetSymbolAddress((void**)&Woh, g_Woh);
    cudaGetSymbolAddress((void**)&Wol, g_Wol);

    cudaFuncSetAttribute(gemm_tc, cudaFuncAttributeMaxDynamicSharedMemorySize,
                         GSMEM_SZ);

    // Prepass conversions
    const int nx4 = MTOT * E_ / 4;   // 2097152
    const int nw4 = E_ * E_ / 4;     // 262144
    convert_split<<<nx4 / 256, 256>>>(xq, xqh, xql, nx4);
    convert_split<<<nx4 / 256, 256>>>(xk, xkh, xkl, nx4);
    convert_split<<<nx4 / 256, 256>>>(xv, xvh, xvl, nx4);
    convert_split<<<nw4 / 256, 256>>>(Wq, Wqh, Wql, nw4);
    convert_split<<<nw4 / 256, 256>>>(Wk, Wkh, Wkl, nw4);
    convert_split<<<nw4 / 256, 256>>>(Wv, Wvh, Wvl, nw4);
    convert_split<<<nw4 / 256, 256>>>(Wo, Woh, Wol, nw4);

    dim3 gblock(256);
    dim3 ggrid(E_ / BN, MTOT / BM);        // (8, 64)

    gemm_tc<<<ggrid, gblock, GSMEM_SZ>>>(xqh, xql, Wqh, Wql, nullptr, Qb, E_);
    gemm_tc<<<ggrid, gblock, GSMEM_SZ>>>(xkh, xkl, Wkh, Wkl, nullptr, Kb, E_);
    gemm_tc<<<ggrid, gblock, GSMEM_SZ>>>(xvh, xvl, Wvh, Wvl, nullptr, Vb, E_);

    dim3 agrid(N_ / 64, H_, B_);           // (32, 16, 4)
    attn_kernel<<<agrid, gblock>>>(Qb, Kb, Vb, Ah, Al);

    gemm_tc<<<ggrid, gblock, GSMEM_SZ>>>(Ah, Al, Woh, Wol, bo, out, E_);
}

// round 7
// speedup vs baseline: 2.3520x; 1.6435x over previous
#include <cuda_runtime.h>
#include <cuda_bf16.h>
#include <cstdint>

#define B_ 4
#define N_ 2048
#define E_ 1024
#define H_ 16
#define D_ 64
#define SCALE_ 0.125f   // 1/sqrt(64)
#define MTOT (B_ * N_)  // 8192

// ---------------------------------------------------------------------------
// Scratch (allocation-free rule: __device__ globals)
// ---------------------------------------------------------------------------
__device__ __nv_bfloat16 g_xqh[(size_t)MTOT * E_];
__device__ __nv_bfloat16 g_xql[(size_t)MTOT * E_];
__device__ __nv_bfloat16 g_xkh[(size_t)MTOT * E_];
__device__ __nv_bfloat16 g_xkl[(size_t)MTOT * E_];
__device__ __nv_bfloat16 g_xvh[(size_t)MTOT * E_];
__device__ __nv_bfloat16 g_xvl[(size_t)MTOT * E_];

__device__ __nv_bfloat16 g_Qh[(size_t)MTOT * E_];
__device__ __nv_bfloat16 g_Ql[(size_t)MTOT * E_];
__device__ __nv_bfloat16 g_Kh[(size_t)MTOT * E_];
__device__ __nv_bfloat16 g_Kl[(size_t)MTOT * E_];
__device__ __nv_bfloat16 g_Vh[(size_t)MTOT * E_];
__device__ __nv_bfloat16 g_Vl[(size_t)MTOT * E_];
__device__ __nv_bfloat16 g_Ah[(size_t)MTOT * E_];
__device__ __nv_bfloat16 g_Al[(size_t)MTOT * E_];

__device__ __nv_bfloat16 g_Wqh[(size_t)E_ * E_];
__device__ __nv_bfloat16 g_Wql[(size_t)E_ * E_];
__device__ __nv_bfloat16 g_Wkh[(size_t)E_ * E_];
__device__ __nv_bfloat16 g_Wkl[(size_t)E_ * E_];
__device__ __nv_bfloat16 g_Wvh[(size_t)E_ * E_];
__device__ __nv_bfloat16 g_Wvl[(size_t)E_ * E_];
__device__ __nv_bfloat16 g_Woh[(size_t)E_ * E_];
__device__ __nv_bfloat16 g_Wol[(size_t)E_ * E_];

// ---------------------------------------------------------------------------
// helpers
// ---------------------------------------------------------------------------
__device__ __forceinline__ uint32_t smem_u32(const void* p) {
    uint32_t a;
    asm("{ .reg .u64 t; cvta.to.shared.u64 t, %1; cvt.u32.u64 %0, t; }"
        : "=r"(a) : "l"(p));
    return a;
}
__device__ __forceinline__ void cp16(uint32_t sa, const void* ga) {
    asm volatile("cp.async.cg.shared.global [%0], [%1], 16;"
                 :: "r"(sa), "l"(ga));
}
__device__ __forceinline__ void cp_commit() {
    asm volatile("cp.async.commit_group;");
}
__device__ __forceinline__ void cp_wait1() {
    asm volatile("cp.async.wait_group 1;");
}
__device__ __forceinline__ void cp_wait0() {
    asm volatile("cp.async.wait_group 0;");
}
__device__ __forceinline__ void ldmx4(uint32_t& r0, uint32_t& r1,
                                      uint32_t& r2, uint32_t& r3, uint32_t a) {
    asm volatile("ldmatrix.sync.aligned.m8n8.x4.shared.b16 {%0,%1,%2,%3}, [%4];"
                 : "=r"(r0), "=r"(r1), "=r"(r2), "=r"(r3) : "r"(a));
}
__device__ __forceinline__ void ldmx4t(uint32_t& r0, uint32_t& r1,
                                       uint32_t& r2, uint32_t& r3, uint32_t a) {
    asm volatile("ldmatrix.sync.aligned.m8n8.x4.trans.shared.b16 {%0,%1,%2,%3}, [%4];"
                 : "=r"(r0), "=r"(r1), "=r"(r2), "=r"(r3) : "r"(a));
}
__device__ __forceinline__ void mma16816(float* d, const uint32_t* a,
                                         const uint32_t* b) {
    asm volatile(
        "mma.sync.aligned.m16n8k16.row.col.f32.bf16.bf16.f32 "
        "{%0,%1,%2,%3}, {%4,%5,%6,%7}, {%8,%9}, {%0,%1,%2,%3};"
        : "+f"(d[0]), "+f"(d[1]), "+f"(d[2]), "+f"(d[3])
        : "r"(a[0]), "r"(a[1]), "r"(a[2]), "r"(a[3]), "r"(b[0]), "r"(b[1]));
}
// split (a,b) into bf16x2 hi + lo words
__device__ __forceinline__ void split2(float a, float b, uint32_t& hi, uint32_t& lo) {
    __nv_bfloat162 h = __floats2bfloat162_rn(a, b);
    __nv_bfloat162 l = __floats2bfloat162_rn(
        a - __bfloat162float(h.x), b - __bfloat162float(h.y));
    hi = *(uint32_t*)&h;
    lo = *(uint32_t*)&l;
}

// ---------------------------------------------------------------------------
// Prepass: fp32 -> (hi, lo) bf16 split.
// ---------------------------------------------------------------------------
__global__ __launch_bounds__(256) void convert_split(
    const float* __restrict__ src, __nv_bfloat16* __restrict__ h,
    __nv_bfloat16* __restrict__ l, int n4)
{
    int i = blockIdx.x * 256 + threadIdx.x;
    if (i >= n4) return;
    float4 v = ((const float4*)src)[i];
    uint32_t h01, l01, h23, l23;
    split2(v.x, v.y, h01, l01);
    split2(v.z, v.w, h23, l23);
    ((uint2*)h)[i] = make_uint2(h01, h23);
    ((uint2*)l)[i] = make_uint2(l01, l23);
}

// ===========================================================================
// HMMA GEMM: C = (Xh+Xl) @ (Wh+Wl)^T, fp32 accum, 3 split products.
// Epilogue: either fp32 (+bias) to Cf, or (hi,lo) bf16 to Oh/Ol (scaled).
// ===========================================================================
#define BM 128
#define BN 128
#define BKC 32
#define KTOT 1024
#define NCHUNK (KTOT / BKC)
#define LDT 40
#define TILE_B (128 * LDT * 2)
#define STAGE_B (4 * TILE_B)
#define GSMEM_SZ (2 * STAGE_B)

__device__ __forceinline__ uint32_t lm_addr(uint32_t base_b, int row0, int kseg0) {
    int L = threadIdx.x & 31;
    int mat = L >> 3;
    int r = (L & 7) + ((mat & 1) << 3);
    int ks = kseg0 + (mat >> 1);
    return base_b + (uint32_t)(row0 + r) * (LDT * 2) + ks * 16;
}

__global__ __launch_bounds__(256) void gemm_tc(
    const __nv_bfloat16* __restrict__ Xh, const __nv_bfloat16* __restrict__ Xl,
    const __nv_bfloat16* __restrict__ Wh, const __nv_bfloat16* __restrict__ Wl,
    const float* __restrict__ bias, float* __restrict__ Cf,
    __nv_bfloat16* __restrict__ Oh, __nv_bfloat16* __restrict__ Ol,
    float scale, int Nn)
{
    extern __shared__ char dynsm[];
    const uint32_t smb = smem_u32(dynsm);
    const int tid = threadIdx.x;
    const int bm = blockIdx.y * BM;
    const int bn = blockIdx.x * BN;
    const int w = tid >> 5;
    const int wm = w >> 2;
    const int wn = w & 3;

    const char* tb[4];
    tb[0] = (const char*)(Xh + (size_t)bm * KTOT);
    tb[1] = (const char*)(Xl + (size_t)bm * KTOT);
    tb[2] = (const char*)(Wh + (size_t)bn * KTOT);
    tb[3] = (const char*)(Wl + (size_t)bn * KTOT);

    float acc[4][4][4];
#pragma unroll
    for (int i = 0; i < 4; i++)
#pragma unroll
        for (int j = 0; j < 4; j++)
#pragma unroll
            for (int t = 0; t < 4; t++) acc[i][j][t] = 0.f;

    auto issue = [&](int c, int s) {
#pragma unroll
        for (int i = 0; i < 8; i++) {
            int sid = tid + 256 * i;
            int tile = sid >> 9;
            int r = (sid >> 2) & 127;
            int seg = sid & 3;
            const char* base = (tile == 0) ? tb[0] : (tile == 1) ? tb[1]
                             : (tile == 2) ? tb[2] : tb[3];
            uint32_t sa = smb + (uint32_t)s * STAGE_B + (uint32_t)tile * TILE_B
                        + (uint32_t)r * (LDT * 2) + seg * 16;
            const char* ga = base + (size_t)r * (KTOT * 2) + c * (BKC * 2) + seg * 16;
            cp16(sa, ga);
        }
        cp_commit();
    };

    issue(0, 0);

    for (int c = 0; c < NCHUNK; c++) {
        const int st = c & 1;
        if (c + 1 < NCHUNK) {
            issue(c + 1, st ^ 1);
            cp_wait1();
        } else {
            cp_wait0();
        }
        __syncthreads();

        const uint32_t bXh = smb + (uint32_t)st * STAGE_B;
        const uint32_t bXl = bXh + TILE_B;
        const uint32_t bWh = bXh + 2 * TILE_B;
        const uint32_t bWl = bXh + 3 * TILE_B;

#pragma unroll
        for (int ks = 0; ks < 2; ks++) {
            const int kseg0 = ks * 2;
            uint32_t ah[4][4], al[4][4], bh[4][2], bl[4][2];
#pragma unroll
            for (int mt = 0; mt < 4; mt++) {
                ldmx4(ah[mt][0], ah[mt][1], ah[mt][2], ah[mt][3],
                      lm_addr(bXh, wm * 64 + mt * 16, kseg0));
                ldmx4(al[mt][0], al[mt][1], al[mt][2], al[mt][3],
                      lm_addr(bXl, wm * 64 + mt * 16, kseg0));
            }
#pragma unroll
            for (int np = 0; np < 2; np++) {
                uint32_t r0, r1, r2, r3;
                ldmx4(r0, r1, r2, r3, lm_addr(bWh, wn * 32 + np * 16, kseg0));
                bh[np * 2 + 0][0] = r0; bh[np * 2 + 0][1] = r2;
                bh[np * 2 + 1][0] = r1; bh[np * 2 + 1][1] = r3;
                ldmx4(r0, r1, r2, r3, lm_addr(bWl, wn * 32 + np * 16, kseg0));
                bl[np * 2 + 0][0] = r0; bl[np * 2 + 0][1] = r2;
                bl[np * 2 + 1][0] = r1; bl[np * 2 + 1][1] = r3;
            }
#pragma unroll
            for (int mt = 0; mt < 4; mt++)
#pragma unroll
                for (int nt = 0; nt < 4; nt++) {
                    mma16816(acc[mt][nt], ah[mt], bh[nt]);
                    mma16816(acc[mt][nt], ah[mt], bl[nt]);
                    mma16816(acc[mt][nt], al[mt], bh[nt]);
                }
        }
        __syncthreads();
    }

    const int lid = tid & 31;
    const int grp = lid >> 2;
    const int tig = lid & 3;
#pragma unroll
    for (int mt = 0; mt < 4; mt++) {
#pragma unroll
        for (int nt = 0; nt < 4; nt++) {
            int row = bm + wm * 64 + mt * 16 + grp;
            int col = bn + wn * 32 + nt * 8 + tig * 2;
            float a0 = acc[mt][nt][0] * scale, a1 = acc[mt][nt][1] * scale;
            float a2 = acc[mt][nt][2] * scale, a3 = acc[mt][nt][3] * scale;
            if (Cf != nullptr) {
                if (bias != nullptr) {
                    float b0 = bias[col], b1 = bias[col + 1];
                    a0 += b0; a1 += b1; a2 += b0; a3 += b1;
                }
                *(float2*)(Cf + (size_t)row * Nn + col) = make_float2(a0, a1);
                *(float2*)(Cf + (size_t)(row + 8) * Nn + col) = make_float2(a2, a3);
            } else {
                uint32_t hi, lo;
                split2(a0, a1, hi, lo);
                *(uint32_t*)(Oh + (size_t)row * Nn + col) = hi;
                *(uint32_t*)(Ol + (size_t)row * Nn + col) = lo;
                split2(a2, a3, hi, lo);
                *(uint32_t*)(Oh + (size_t)(row + 8) * Nn + col) = hi;
                *(uint32_t*)(Ol + (size_t)(row + 8) * Nn + col) = lo;
            }
        }
    }
}

// ===========================================================================
// Tensor-core causal flash attention (FA2 layout), bf16 hi/lo.
// Block: 64 q-rows of one (b,h); 4 warps, each a 16-row strip.
// S = Qh*Kh + Qh*Kl + Ql*Kh (scale folded into Q); online softmax on frags;
// O += Ph*Vh + Ph*Vl + Pl*Vh with V via ldmatrix.trans.
// K/V tiles double-buffered with cp.async.
// ===========================================================================
#define ALDT 144               // smem row stride bytes (72 u16)
#define AT_TILE (64 * ALDT)    // 9216
#define AOFF_QH 0
#define AOFF_QL AT_TILE
#define AOFF_ST (2 * AT_TILE)
#define ASTAGE (4 * AT_TILE)
#define ASMEM (AOFF_ST + 2 * ASTAGE)   // 92160

__device__ __forceinline__ uint32_t lda(uint32_t base, int r0, int c0) {
    int L = threadIdx.x & 31;
    int mat = L >> 3;
    int r = r0 + (L & 7) + ((mat & 1) << 3);
    int c = c0 + ((mat >> 1) << 3);
    return base + (uint32_t)r * ALDT + c * 2;
}

__global__ __launch_bounds__(128) void attn_mma(
    const __nv_bfloat16* __restrict__ Qh, const __nv_bfloat16* __restrict__ Ql,
    const __nv_bfloat16* __restrict__ Kh, const __nv_bfloat16* __restrict__ Kl,
    const __nv_bfloat16* __restrict__ Vh, const __nv_bfloat16* __restrict__ Vl,
    __nv_bfloat16* __restrict__ Oh, __nv_bfloat16* __restrict__ Ol)
{
    extern __shared__ char dynsm[];
    const uint32_t smb = smem_u32(dynsm);
    const int tid = threadIdx.x;
    const int w = tid >> 5;
    const int lid = tid & 31;
    const int grp = lid >> 2;
    const int tig = lid & 3;
    const int iblk = blockIdx.x;
    const int h = blockIdx.y;
    const int b = blockIdx.z;
    const int qbase = iblk * 64;
    const size_t bN = (size_t)b * N_;

    auto issue_stage = [&](int s, int kbase) {
#pragma unroll
        for (int i = 0; i < 16; i++) {
            int sid = tid + 128 * i;          // 0..2047
            int tile = sid >> 9;              // 0 Kh,1 Kl,2 Vh,3 Vl
            int r = (sid >> 3) & 63;
            int seg = sid & 7;
            const __nv_bfloat16* gp = (tile == 0) ? Kh : (tile == 1) ? Kl
                                    : (tile == 2) ? Vh : Vl;
            const char* ga = (const char*)(gp + (bN + kbase + r) * E_ + h * 64)
                           + seg * 16;
            cp16(smb + AOFF_ST + (uint32_t)s * ASTAGE + (uint32_t)tile * AT_TILE
                 + (uint32_t)r * ALDT + seg * 16, ga);
        }
        cp_commit();
    };

    // prologue: Q tiles + stage 0 (one group)
    {
#pragma unroll
        for (int i = 0; i < 8; i++) {
            int sid = tid + 128 * i;          // 0..1023
            int tile = sid >> 9;              // 0 Qh, 1 Ql
            int r = (sid >> 3) & 63;
            int seg = sid & 7;
            const __nv_bfloat16* gp = tile ? Ql : Qh;
            const char* ga = (const char*)(gp + (bN + qbase + r) * E_ + h * 64)
                           + seg * 16;
            cp16(smb + (tile ? AOFF_QL : AOFF_QH) + (uint32_t)r * ALDT + seg * 16, ga);
        }
    }
    issue_stage(0, 0);

    uint32_t qh[4][4], ql[4][4];
    float o[8][4];
#pragma unroll
    for (int t = 0; t < 8; t++)
#pragma unroll
        for (int c = 0; c < 4; c++) o[t][c] = 0.f;
    float mr0 = -1e30f, mr1 = -1e30f, lr0 = 0.f, lr1 = 0.f;

    for (int j = 0; j <= iblk; j++) {
        cp_wait0();
        __syncthreads();
        if (j == 0) {
#pragma unroll
            for (int kc = 0; kc < 4; kc++) {
                ldmx4(qh[kc][0], qh[kc][1], qh[kc][2], qh[kc][3],
                      lda(smb + AOFF_QH, w * 16, kc * 16));
                ldmx4(ql[kc][0], ql[kc][1], ql[kc][2], ql[kc][3],
                      lda(smb + AOFF_QL, w * 16, kc * 16));
            }
        }
        if (j < iblk) issue_stage((j + 1) & 1, (j + 1) * 64);

        const uint32_t bKH = smb + AOFF_ST + (uint32_t)(j & 1) * ASTAGE;
        const uint32_t bKL = bKH + AT_TILE;
        const uint32_t bVH = bKH + 2 * AT_TILE;
        const uint32_t bVL = bKH + 3 * AT_TILE;

        // ---- S = Q K^T (3 split products), scale pre-folded into Q ----
        float s[8][4];
#pragma unroll
        for (int t = 0; t < 8; t++)
#pragma unroll
            for (int c = 0; c < 4; c++) s[t][c] = 0.f;
#pragma unroll
        for (int kc = 0; kc < 4; kc++) {
#pragma unroll
            for (int np = 0; np < 4; np++) {
                uint32_t r0, r1, r2, r3, t0, t1, t2, t3;
                ldmx4(r0, r1, r2, r3, lda(bKH, np * 16, kc * 16));
                ldmx4(t0, t1, t2, t3, lda(bKL, np * 16, kc * 16));
                uint32_t bh0[2] = {r0, r2}, bh1[2] = {r1, r3};
                uint32_t bl0[2] = {t0, t2}, bl1[2] = {t1, t3};
                mma16816(s[np * 2 + 0], qh[kc], bh0);
                mma16816(s[np * 2 + 0], qh[kc], bl0);
                mma16816(s[np * 2 + 0], ql[kc], bh0);
                mma16816(s[np * 2 + 1], qh[kc], bh1);
                mma16816(s[np * 2 + 1], qh[kc], bl1);
                mma16816(s[np * 2 + 1], ql[kc], bh1);
            }
        }

        // ---- causal mask (diagonal block only) ----
        if (j == iblk) {
            const int row0 = w * 16 + grp;
            const int row1 = row0 + 8;
#pragma unroll
            for (int t = 0; t < 8; t++) {
                int col = t * 8 + 2 * tig;
                if (col > row0) s[t][0] = -1e30f;
                if (col + 1 > row0) s[t][1] = -1e30f;
                if (col > row1) s[t][2] = -1e30f;
                if (col + 1 > row1) s[t][3] = -1e30f;
            }
        }

        // ---- online softmax ----
        float m0 = -1e30f, m1 = -1e30f;
#pragma unroll
        for (int t = 0; t < 8; t++) {
            m0 = fmaxf(m0, fmaxf(s[t][0], s[t][1]));
            m1 = fmaxf(m1, fmaxf(s[t][2], s[t][3]));
        }
        m0 = fmaxf(m0, __shfl_xor_sync(0xffffffffu, m0, 1));
        m0 = fmaxf(m0, __shfl_xor_sync(0xffffffffu, m0, 2));
        m1 = fmaxf(m1, __shfl_xor_sync(0xffffffffu, m1, 1));
        m1 = fmaxf(m1, __shfl_xor_sync(0xffffffffu, m1, 2));
        float mn0 = fmaxf(mr0, m0), mn1 = fmaxf(mr1, m1);
        float a0 = __expf(mr0 - mn0), a1 = __expf(mr1 - mn1);
        mr0 = mn0; mr1 = mn1;
        float sum0 = 0.f, sum1 = 0.f;
#pragma unroll
        for (int t = 0; t < 8; t++) {
            s[t][0] = __expf(s[t][0] - mn0);
            s[t][1] = __expf(s[t][1] - mn0);
            s[t][2] = __expf(s[t][2] - mn1);
            s[t][3] = __expf(s[t][3] - mn1);
            sum0 += s[t][0] + s[t][1];
            sum1 += s[t][2] + s[t][3];
        }
        sum0 += __shfl_xor_sync(0xffffffffu, sum0, 1);
        sum0 += __shfl_xor_sync(0xffffffffu, sum0, 2);
        sum1 += __shfl_xor_sync(0xffffffffu, sum1, 1);
        sum1 += __shfl_xor_sync(0xffffffffu, sum1, 2);
        lr0 = lr0 * a0 + sum0;
        lr1 = lr1 * a1 + sum1;
#pragma unroll
        for (int t = 0; t < 8; t++) {
            o[t][0] *= a0; o[t][1] *= a0;
            o[t][2] *= a1; o[t][3] *= a1;
        }

        // ---- P: C-frag -> A-frag, hi/lo split ----
        uint32_t ph[4][4], pl[4][4];
#pragma unroll
        for (int kc = 0; kc < 4; kc++) {
            split2(s[2 * kc][0], s[2 * kc][1], ph[kc][0], pl[kc][0]);
            split2(s[2 * kc][2], s[2 * kc][3], ph[kc][1], pl[kc][1]);
            split2(s[2 * kc + 1][0], s[2 * kc + 1][1], ph[kc][2], pl[kc][2]);
            split2(s[2 * kc + 1][2], s[2 * kc + 1][3], ph[kc][3], pl[kc][3]);
        }

        // ---- O += P V (3 split products), V via ldmatrix.trans ----
#pragma unroll
        for (int kc = 0; kc < 4; kc++) {
#pragma unroll
            for (int nd = 0; nd < 4; nd++) {
                uint32_t r0, r1, r2, r3, t0, t1, t2, t3;
                ldmx4t(r0, r1, r2, r3, lda(bVH, kc * 16, nd * 16));
                ldmx4t(t0, t1, t2, t3, lda(bVL, kc * 16, nd * 16));
                uint32_t vh0[2] = {r0, r1}, vh1[2] = {r2, r3};
                uint32_t vl0[2] = {t0, t1}, vl1[2] = {t2, t3};
                mma16816(o[nd * 2 + 0], ph[kc], vh0);
                mma16816(o[nd * 2 + 0], ph[kc], vl0);
                mma16816(o[nd * 2 + 0], pl[kc], vh0);
                mma16816(o[nd * 2 + 1], ph[kc], vh1);
                mma16816(o[nd * 2 + 1], ph[kc], vl1);
                mma16816(o[nd * 2 + 1], pl[kc], vh1);
            }
        }
    }

    // ---- epilogue: normalize, hi/lo split, store [B,N,E] ----
    const float i0 = 1.f / lr0, i1 = 1.f / lr1;
    const int qr0 = qbase + w * 16 + grp;
    const size_t ro0 = (bN + qr0) * E_;
    const size_t ro1 = (bN + qr0 + 8) * E_;
#pragma unroll
    for (int t = 0; t < 8; t++) {
        int col = h * 64 + t * 8 + 2 * tig;
        uint32_t hi, lo;
        split2(o[t][0] * i0, o[t][1] * i0, hi, lo);
        *(uint32_t*)(Oh + ro0 + col) = hi;
        *(uint32_t*)(Ol + ro0 + col) = lo;
        split2(o[t][2] * i1, o[t][3] * i1, hi, lo);
        *(uint32_t*)(Oh + ro1 + col) = hi;
        *(uint32_t*)(Ol + ro1 + col) = lo;
    }
}

// ---------------------------------------------------------------------------
extern "C" void kernel_launch(void* const* d_in, const int* in_sizes, int n_in,
                              void* d_out, int out_size)
{
    const float* xq = (const float*)d_in[0];
    const float* xk = (const float*)d_in[1];
    const float* xv = (const float*)d_in[2];
    // d_in[3] = attn_mask (causal, recomputed analytically) — unused
    const float* Wq = (const float*)d_in[4];
    const float* Wk = (const float*)d_in[5];
    const float* Wv = (const float*)d_in[6];
    const float* Wo = (const float*)d_in[7];
    const float* bo = (const float*)d_in[8];
    float* out = (float*)d_out;

    __nv_bfloat16 *xqh, *xql, *xkh, *xkl, *xvh, *xvl;
    __nv_bfloat16 *Qh, *Ql, *Kh, *Kl, *Vh, *Vl, *Ah, *Al;
    __nv_bfloat16 *Wqh, *Wql, *Wkh, *Wkl, *Wvh, *Wvl, *Woh, *Wol;
    cudaGetSymbolAddress((void**)&xqh, g_xqh);
    cudaGetSymbolAddress((void**)&xql, g_xql);
    cudaGetSymbolAddress((void**)&xkh, g_xkh);
    cudaGetSymbolAddress((void**)&xkl, g_xkl);
    cudaGetSymbolAddress((void**)&xvh, g_xvh);
    cudaGetSymbolAddress((void**)&xvl, g_xvl);
    cudaGetSymbolAddress((void**)&Qh, g_Qh);
    cudaGetSymbolAddress((void**)&Ql, g_Ql);
    cudaGetSymbolAddress((void**)&Kh, g_Kh);
    cudaGetSymbolAddress((void**)&Kl, g_Kl);
    cudaGetSymbolAddress((void**)&Vh, g_Vh);
    cudaGetSymbolAddress((void**)&Vl, g_Vl);
    cudaGetSymbolAddress((void**)&Ah, g_Ah);
    cudaGetSymbolAddress((void**)&Al, g_Al);
    cudaGetSymbolAddress((void**)&Wqh, g_Wqh);
    cudaGetSymbolAddress((void**)&Wql, g_Wql);
    cudaGetSymbolAddress((void**)&Wkh, g_Wkh);
    cudaGetSymbolAddress((void**)&Wkl, g_Wkl);
    cudaGetSymbolAddress((void**)&Wvh, g_Wvh);
    cudaGetSymbolAddress((void**)&Wvl, g_Wvl);
    cudaGetSymbolAddress((void**)&Woh, g_Woh);
    cudaGetSymbolAddress((void**)&Wol, g_Wol);

    cudaFuncSetAttribute(gemm_tc, cudaFuncAttributeMaxDynamicSharedMemorySize,
                         GSMEM_SZ);
    cudaFuncSetAttribute(attn_mma, cudaFuncAttributeMaxDynamicSharedMemorySize,
                         ASMEM);

    // Prepass conversions
    const int nx4 = MTOT * E_ / 4;
    const int nw4 = E_ * E_ / 4;
    convert_split<<<nx4 / 256, 256>>>(xq, xqh, xql, nx4);
    convert_split<<<nx4 / 256, 256>>>(xk, xkh, xkl, nx4);
    convert_split<<<nx4 / 256, 256>>>(xv, xvh, xvl, nx4);
    convert_split<<<nw4 / 256, 256>>>(Wq, Wqh, Wql, nw4);
    convert_split<<<nw4 / 256, 256>>>(Wk, Wkh, Wkl, nw4);
    convert_split<<<nw4 / 256, 256>>>(Wv, Wvh, Wvl, nw4);
    convert_split<<<nw4 / 256, 256>>>(Wo, Woh, Wol, nw4);

    dim3 gblock(256);
    dim3 ggrid(E_ / BN, MTOT / BM);        // (8, 64)

    // Projections -> bf16 hi/lo (Q pre-scaled by 1/sqrt(D))
    gemm_tc<<<ggrid, gblock, GSMEM_SZ>>>(xqh, xql, Wqh, Wql, nullptr, nullptr,
                                         Qh, Ql, SCALE_, E_);
    gemm_tc<<<ggrid, gblock, GSMEM_SZ>>>(xkh, xkl, Wkh, Wkl, nullptr, nullptr,
                                         Kh, Kl, 1.0f, E_);
    gemm_tc<<<ggrid, gblock, GSMEM_SZ>>>(xvh, xvl, Wvh, Wvl, nullptr, nullptr,
                                         Vh, Vl, 1.0f, E_);

    dim3 agrid(N_ / 64, H_, B_);           // (32, 16, 4)
    attn_mma<<<agrid, 128, ASMEM>>>(Qh, Ql, Kh, Kl, Vh, Vl, Ah, Al);

    // Output projection -> fp32 + bias
    gemm_tc<<<ggrid, gblock, GSMEM_SZ>>>(Ah, Al, Woh, Wol, bo, out,
                                         nullptr, nullptr, 1.0f, E_);
}